// round 16
// baseline (speedup 1.0000x reference)
#include <cuda_runtime.h>
#include <cuda_bf16.h>
#include <cstdint>

#define T_DIM 4096
#define K_DIM 16384
#define HCN 4
#define N_OUT 24
#define KSPLIT 8
#define KCHUNK 2048
#define NKS 128          // k16 steps per chunk
#define NTHREADS 256

// Device globals (no allocation allowed)
__device__ float g_hpart[KSPLIT][T_DIM][32];   // 24 used, padded to 32
__device__ float g_sspart[KSPLIT][T_DIM];
__device__ uint4 g_wfrag[1024 * 32 * 3];       // per-lane B fragments, 1.5MB

// ---------------- helpers ----------------
__device__ __forceinline__ uint32_t pack_hi(float v0, float v1, float& l0, float& l1) {
    uint32_t h0 = __float_as_uint(v0) & 0xffff0000u;
    uint32_t h1 = __float_as_uint(v1) & 0xffff0000u;
    l0 = v0 - __uint_as_float(h0);
    l1 = v1 - __uint_as_float(h1);
    return (h0 >> 16) | h1;   // lower 16 = v0(hi), upper 16 = v1(hi)
}
__device__ __forceinline__ uint32_t pack_bf2(float lo_elem, float hi_elem) {
    uint32_t d;
    asm("cvt.rn.bf16x2.f32 %0, %1, %2;" : "=r"(d) : "f"(hi_elem), "f"(lo_elem));
    return d;
}
__device__ __forceinline__ float frcp(float a) {
    float r;
    asm("rcp.approx.f32 %0, %1;" : "=f"(r) : "f"(a));
    return r;
}
#define MMA(d, a0, a1, a2, a3, b0, b1)                                        \
    asm volatile("mma.sync.aligned.m16n8k16.row.col.f32.bf16.bf16.f32 "       \
                 "{%0,%1,%2,%3}, {%4,%5,%6,%7}, {%8,%9}, {%0,%1,%2,%3};"      \
                 : "+f"(d[0]), "+f"(d[1]), "+f"(d[2]), "+f"(d[3])             \
                 : "r"(a0), "r"(a1), "r"(a2), "r"(a3), "r"(b0), "r"(b1))

// ---------------------------------------------------------------------------
// Kernel W: precompute B fragments (hi/lo bf16) in mma.sync per-lane order.
// Reshaped: 128 blocks x 256 threads (8 tiles per block, one warp per tile).
// ---------------------------------------------------------------------------
extern "C" __global__ void __launch_bounds__(256)
mhc_wconv_kernel(const float* __restrict__ w) {
    const int t = blockIdx.x * 8 + (threadIdx.x >> 5);   // k16 tile 0..1023
    const int lane = threadIdx.x & 31;
    const int k0 = (lane & 3) * 2;
    const int rowq = lane >> 2;
#pragma unroll
    for (int nt = 0; nt < 3; nt++) {
        int col = nt * 8 + rowq;
        const float* wb = w + (size_t)(t * 16) * N_OUT + col;
        float v00 = wb[(k0 + 0) * N_OUT], v01 = wb[(k0 + 1) * N_OUT];
        float v08 = wb[(k0 + 8) * N_OUT], v09 = wb[(k0 + 9) * N_OUT];
        float l00, l01, l08, l09;
        uint32_t bhi0 = pack_hi(v00, v01, l00, l01);
        uint32_t bhi1 = pack_hi(v08, v09, l08, l09);
        uint32_t blo0 = pack_bf2(l00, l01);
        uint32_t blo1 = pack_bf2(l08, l09);
        g_wfrag[(t * 32 + lane) * 3 + nt] = make_uint4(bhi0, bhi1, blo0, blo1);
    }
}

// ---------------------------------------------------------------------------
// Kernel A: mma.sync bf16 3-split GEMM (unchanged from R14 — at the HMMA
// throughput floor). Grid (32, 8); warp owns 16 rows x 2048 k; 9 HMMA per
// k16 step (3 ntiles x {AhiBhi, AhiBlo, AloBhi}); exact fp32 ss on the fly.
// ---------------------------------------------------------------------------
extern "C" __global__ void __launch_bounds__(NTHREADS)
mhc_gemm_kernel(const float* __restrict__ x) {
    const int tid = threadIdx.x;
    const int wid = tid >> 5;
    const int lane = tid & 31;
    const int bm = blockIdx.x;
    const int bk = blockIdx.y;

    const int r0 = bm * 128 + wid * 16 + (lane >> 2);
    const int r1 = r0 + 8;
    const int k0 = (lane & 3) * 2;
    const float* px0 = x + (size_t)r0 * K_DIM + bk * KCHUNK + k0;
    const float* px1 = x + (size_t)r1 * K_DIM + bk * KCHUNK + k0;
    const uint4* bfr = g_wfrag + ((size_t)(bk * NKS) * 32 + lane) * 3;

    float acc[3][4];
#pragma unroll
    for (int nt = 0; nt < 3; nt++)
#pragma unroll
        for (int j = 0; j < 4; j++) acc[nt][j] = 0.f;
    float ss0 = 0.f, ss1 = 0.f;

#pragma unroll 4
    for (int ks = 0; ks < NKS; ks++) {
        float2 x00 = __ldcs((const float2*)(px0 + ks * 16));
        float2 x01 = __ldcs((const float2*)(px0 + ks * 16 + 8));
        float2 x10 = __ldcs((const float2*)(px1 + ks * 16));
        float2 x11 = __ldcs((const float2*)(px1 + ks * 16 + 8));
        uint4 b0 = bfr[ks * 96 + 0];
        uint4 b1 = bfr[ks * 96 + 1];
        uint4 b2 = bfr[ks * 96 + 2];

        float l00, l01, l02, l03, l10, l11, l12, l13;
        uint32_t ah0 = pack_hi(x00.x, x00.y, l00, l01);
        uint32_t ah1 = pack_hi(x10.x, x10.y, l10, l11);
        uint32_t ah2 = pack_hi(x01.x, x01.y, l02, l03);
        uint32_t ah3 = pack_hi(x11.x, x11.y, l12, l13);
        uint32_t al0 = pack_bf2(l00, l01);
        uint32_t al1 = pack_bf2(l10, l11);
        uint32_t al2 = pack_bf2(l02, l03);
        uint32_t al3 = pack_bf2(l12, l13);

        ss0 = fmaf(x00.x, x00.x, fmaf(x00.y, x00.y,
              fmaf(x01.x, x01.x, fmaf(x01.y, x01.y, ss0))));
        ss1 = fmaf(x10.x, x10.x, fmaf(x10.y, x10.y,
              fmaf(x11.x, x11.x, fmaf(x11.y, x11.y, ss1))));

        MMA(acc[0], ah0, ah1, ah2, ah3, b0.x, b0.y);
        MMA(acc[0], ah0, ah1, ah2, ah3, b0.z, b0.w);
        MMA(acc[0], al0, al1, al2, al3, b0.x, b0.y);
        MMA(acc[1], ah0, ah1, ah2, ah3, b1.x, b1.y);
        MMA(acc[1], ah0, ah1, ah2, ah3, b1.z, b1.w);
        MMA(acc[1], al0, al1, al2, al3, b1.x, b1.y);
        MMA(acc[2], ah0, ah1, ah2, ah3, b2.x, b2.y);
        MMA(acc[2], ah0, ah1, ah2, ah3, b2.z, b2.w);
        MMA(acc[2], al0, al1, al2, al3, b2.x, b2.y);
    }

#pragma unroll
    for (int nt = 0; nt < 3; nt++) {
        int col = nt * 8 + (lane & 3) * 2;
        *(float2*)&g_hpart[bk][r0][col] = make_float2(acc[nt][0], acc[nt][1]);
        *(float2*)&g_hpart[bk][r1][col] = make_float2(acc[nt][2], acc[nt][3]);
    }
    ss0 += __shfl_xor_sync(0xffffffffu, ss0, 1);
    ss0 += __shfl_xor_sync(0xffffffffu, ss0, 2);
    ss1 += __shfl_xor_sync(0xffffffffu, ss1, 1);
    ss1 += __shfl_xor_sync(0xffffffffu, ss1, 2);
    if ((lane & 3) == 0) {
        g_sspart[bk][r0] = ss0;
        g_sspart[bk][r1] = ss1;
    }
}

// ---------------------------------------------------------------------------
// Kernel B: reduce partials, activations, Sinkhorn. FIXED 400 iterations
// (= reference MAX_IT^2, exact trajectory match — the old early-exit almost
// never fired because ~27% of rows converge slower than 0.995/iter, so every
// warp ran 400 anyway while the snapshot/compare/branch blocked scheduling).
// Tree-form dot products shorten the per-iter critical path (12 vs 16 cyc
// per chain); MUFU floor is 8 rcp x 8 cyc = 64 cyc/iter.
// ---------------------------------------------------------------------------
extern "C" __global__ void __launch_bounds__(32)
mhc_finish_kernel(const float* __restrict__ bias, const float* __restrict__ alpha,
                  float* __restrict__ out) {
    int row = blockIdx.x * 32 + threadIdx.x;

    float h[N_OUT];
#pragma unroll
    for (int n = 0; n < N_OUT; n++) h[n] = 0.f;
#pragma unroll
    for (int c = 0; c < KSPLIT; c++) {
        const float4* hp = (const float4*)g_hpart[c][row];
#pragma unroll
        for (int q = 0; q < 6; q++) {
            float4 v4 = hp[q];
            h[q * 4 + 0] += v4.x;
            h[q * 4 + 1] += v4.y;
            h[q * 4 + 2] += v4.z;
            h[q * 4 + 3] += v4.w;
        }
    }
    float ss = 0.f;
#pragma unroll
    for (int c = 0; c < KSPLIT; c++) ss += g_sspart[c][row];

    float r_inv = rsqrtf(ss * (1.0f / K_DIM));
    float a0 = alpha[0], a1 = alpha[1], a2 = alpha[2];

    float pre[HCN], post[HCN], H[HCN][HCN];
#pragma unroll
    for (int n = 0; n < HCN; n++) {
        float z0 = fmaf(r_inv * a0, h[n], bias[n]);
        pre[n] = 1.f / (1.f + __expf(-z0));
        float z1 = fmaf(r_inv * a1, h[HCN + n], bias[HCN + n]);
        post[n] = 2.f / (1.f + __expf(-z1));
    }
#pragma unroll
    for (int i = 0; i < HCN; i++)
#pragma unroll
        for (int j = 0; j < HCN; j++) {
            float z = fmaf(r_inv * a2, h[8 + 4 * i + j], bias[8 + 4 * i + j]);
            H[i][j] = __expf(z);
        }

    const float EPSV = 1e-12f;
    float u0, u1, u2, u3;
    float v0 = 1.f, v1 = 1.f, v2 = 1.f, v3 = 1.f;
#pragma unroll 4
    for (int it = 0; it < 400; it++) {
        // u-phase: nu_i = 1/(H[i,:].v + eps), tree-form dots
        float a_0 = fmaf(H[0][1], v1, H[0][0] * v0);
        float b_0 = fmaf(H[0][3], v3, fmaf(H[0][2], v2, EPSV));
        float a_1 = fmaf(H[1][1], v1, H[1][0] * v0);
        float b_1 = fmaf(H[1][3], v3, fmaf(H[1][2], v2, EPSV));
        float a_2 = fmaf(H[2][1], v1, H[2][0] * v0);
        float b_2 = fmaf(H[2][3], v3, fmaf(H[2][2], v2, EPSV));
        float a_3 = fmaf(H[3][1], v1, H[3][0] * v0);
        float b_3 = fmaf(H[3][3], v3, fmaf(H[3][2], v2, EPSV));
        u0 = frcp(a_0 + b_0);
        u1 = frcp(a_1 + b_1);
        u2 = frcp(a_2 + b_2);
        u3 = frcp(a_3 + b_3);
        // v-phase: v_j = 1/(H[:,j].u + eps)
        float c_0 = fmaf(H[1][0], u1, H[0][0] * u0);
        float d_0 = fmaf(H[3][0], u3, fmaf(H[2][0], u2, EPSV));
        float c_1 = fmaf(H[1][1], u1, H[0][1] * u0);
        float d_1 = fmaf(H[3][1], u3, fmaf(H[2][1], u2, EPSV));
        float c_2 = fmaf(H[1][2], u1, H[0][2] * u0);
        float d_2 = fmaf(H[3][2], u3, fmaf(H[2][2], u2, EPSV));
        float c_3 = fmaf(H[1][3], u1, H[0][3] * u0);
        float d_3 = fmaf(H[3][3], u3, fmaf(H[2][3], u2, EPSV));
        v0 = frcp(c_0 + d_0);
        v1 = frcp(c_1 + d_1);
        v2 = frcp(c_2 + d_2);
        v3 = frcp(c_3 + d_3);
    }

    float u[4] = {u0, u1, u2, u3};
    float v[4] = {v0, v1, v2, v3};

    ((float4*)out)[row] = make_float4(pre[0], pre[1], pre[2], pre[3]);
    ((float4*)(out + (size_t)T_DIM * HCN))[row] =
        make_float4(post[0], post[1], post[2], post[3]);
    float4* res = (float4*)(out + 2 * (size_t)T_DIM * HCN + (size_t)row * 16);
#pragma unroll
    for (int i = 0; i < 4; i++) {
        res[i] = make_float4(u[i] * H[i][0] * v[0], u[i] * H[i][1] * v[1],
                             u[i] * H[i][2] * v[2], u[i] * H[i][3] * v[3]);
    }
}

// ---------------------------------------------------------------------------
extern "C" void kernel_launch(void* const* d_in, const int* in_sizes, int n_in,
                              void* d_out, int out_size) {
    const float* x = (const float*)d_in[0];
    const float* w = (const float*)d_in[1];
    const float* bias = (const float*)d_in[2];
    const float* alpha = (const float*)d_in[3];
    float* out = (float*)d_out;

    mhc_wconv_kernel<<<128, 256>>>(w);
    mhc_gemm_kernel<<<dim3(T_DIM / 128, KSPLIT), NTHREADS>>>(x);
    mhc_finish_kernel<<<T_DIM / 32, 32>>>(bias, alpha, out);
}

// round 17
// speedup vs baseline: 1.3608x; 1.3608x over previous
#include <cuda_runtime.h>
#include <cuda_bf16.h>
#include <cstdint>

#define T_DIM 4096
#define K_DIM 16384
#define HCN 4
#define N_OUT 24
#define KSPLIT 16
#define KCHUNK 1024      // k per CTA
#define NKS 64           // k16 steps per chunk
#define MB 64            // rows per CTA
#define NTHREADS 128     // 4 warps

// Device globals (no allocation allowed)
__device__ float g_hpart[KSPLIT][T_DIM][32];   // 24 used, padded to 32
__device__ float g_sspart[KSPLIT][T_DIM];
__device__ uint4 g_wfrag[1024 * 32 * 3];       // per-lane B fragments, 1.5MB

// ---------------- helpers ----------------
__device__ __forceinline__ uint32_t pack_hi(float v0, float v1, float& l0, float& l1) {
    uint32_t h0 = __float_as_uint(v0) & 0xffff0000u;
    uint32_t h1 = __float_as_uint(v1) & 0xffff0000u;
    l0 = v0 - __uint_as_float(h0);
    l1 = v1 - __uint_as_float(h1);
    return (h0 >> 16) | h1;   // lower 16 = v0(hi), upper 16 = v1(hi)
}
__device__ __forceinline__ uint32_t pack_bf2(float lo_elem, float hi_elem) {
    uint32_t d;
    asm("cvt.rn.bf16x2.f32 %0, %1, %2;" : "=r"(d) : "f"(hi_elem), "f"(lo_elem));
    return d;
}
__device__ __forceinline__ float frcp(float a) {
    float r;
    asm("rcp.approx.f32 %0, %1;" : "=f"(r) : "f"(a));
    return r;
}
#define MMA(d, a0, a1, a2, a3, b0, b1)                                        \
    asm volatile("mma.sync.aligned.m16n8k16.row.col.f32.bf16.bf16.f32 "       \
                 "{%0,%1,%2,%3}, {%4,%5,%6,%7}, {%8,%9}, {%0,%1,%2,%3};"      \
                 : "+f"(d[0]), "+f"(d[1]), "+f"(d[2]), "+f"(d[3])             \
                 : "r"(a0), "r"(a1), "r"(a2), "r"(a3), "r"(b0), "r"(b1))

// ---------------------------------------------------------------------------
// Kernel W: precompute B fragments (hi/lo bf16) with PERMUTED k mapping.
// For k16 tile t, lane (q = lane&3, col = nt*8 + lane>>2): fragment slots map
// to physical k = t*16 + 4q + {0,1} (b0) and + {2,3} (b1). The GEMM applies
// the same permutation on A (one contiguous float4 per lane), so the MMA
// result is the exact same dot product.
// ---------------------------------------------------------------------------
extern "C" __global__ void __launch_bounds__(256)
mhc_wconv_kernel(const float* __restrict__ w) {
    const int t = blockIdx.x * 8 + (threadIdx.x >> 5);   // k16 tile 0..1023
    const int lane = threadIdx.x & 31;
    const int k0 = (lane & 3) * 4;
    const int rowq = lane >> 2;
#pragma unroll
    for (int nt = 0; nt < 3; nt++) {
        int col = nt * 8 + rowq;
        const float* wb = w + (size_t)(t * 16 + k0) * N_OUT + col;
        float v0 = wb[0 * N_OUT], v1 = wb[1 * N_OUT];
        float v2 = wb[2 * N_OUT], v3 = wb[3 * N_OUT];
        float l0, l1, l2, l3;
        uint32_t bhi0 = pack_hi(v0, v1, l0, l1);
        uint32_t bhi1 = pack_hi(v2, v3, l2, l3);
        uint32_t blo0 = pack_bf2(l0, l1);
        uint32_t blo1 = pack_bf2(l2, l3);
        g_wfrag[(t * 32 + lane) * 3 + nt] = make_uint4(bhi0, bhi1, blo0, blo1);
    }
}

// ---------------------------------------------------------------------------
// Kernel A: mma.sync bf16 3-split GEMM. Grid (64, 16), 128 threads (4 warps):
// CTA = 64 rows x 1024 k — small CTAs kill wave quantization (1024 CTAs).
// Per k16 step each thread loads ONE float4 per fragment row (permuted-k),
// converts to hi/lo bf16, and issues 9 HMMA. Exact fp32 ss on the fly.
// ---------------------------------------------------------------------------
extern "C" __global__ void __launch_bounds__(NTHREADS)
mhc_gemm_kernel(const float* __restrict__ x) {
    const int tid = threadIdx.x;
    const int wid = tid >> 5;
    const int lane = tid & 31;
    const int bm = blockIdx.x;
    const int bk = blockIdx.y;

    const int r0 = bm * MB + wid * 16 + (lane >> 2);
    const int r1 = r0 + 8;
    const int k0 = (lane & 3) * 4;    // permuted: contiguous float4 per lane
    const float* px0 = x + (size_t)r0 * K_DIM + bk * KCHUNK + k0;
    const float* px1 = x + (size_t)r1 * K_DIM + bk * KCHUNK + k0;
    const uint4* bfr = g_wfrag + ((size_t)(bk * NKS) * 32 + lane) * 3;

    float acc[3][4];
#pragma unroll
    for (int nt = 0; nt < 3; nt++)
#pragma unroll
        for (int j = 0; j < 4; j++) acc[nt][j] = 0.f;
    float ss0 = 0.f, ss1 = 0.f;

#pragma unroll 4
    for (int ks = 0; ks < NKS; ks++) {
        float4 X0 = __ldcs((const float4*)(px0 + ks * 16));
        float4 X1 = __ldcs((const float4*)(px1 + ks * 16));
        uint4 b0 = bfr[ks * 96 + 0];
        uint4 b1 = bfr[ks * 96 + 1];
        uint4 b2 = bfr[ks * 96 + 2];

        // A fragments (permuted): pair0 = (X.x, X.y), pair1 = (X.z, X.w)
        float l00, l01, l02, l03, l10, l11, l12, l13;
        uint32_t ah0 = pack_hi(X0.x, X0.y, l00, l01);
        uint32_t ah1 = pack_hi(X1.x, X1.y, l10, l11);
        uint32_t ah2 = pack_hi(X0.z, X0.w, l02, l03);
        uint32_t ah3 = pack_hi(X1.z, X1.w, l12, l13);
        uint32_t al0 = pack_bf2(l00, l01);
        uint32_t al1 = pack_bf2(l10, l11);
        uint32_t al2 = pack_bf2(l02, l03);
        uint32_t al3 = pack_bf2(l12, l13);

        ss0 = fmaf(X0.x, X0.x, fmaf(X0.y, X0.y,
              fmaf(X0.z, X0.z, fmaf(X0.w, X0.w, ss0))));
        ss1 = fmaf(X1.x, X1.x, fmaf(X1.y, X1.y,
              fmaf(X1.z, X1.z, fmaf(X1.w, X1.w, ss1))));

        MMA(acc[0], ah0, ah1, ah2, ah3, b0.x, b0.y);
        MMA(acc[0], ah0, ah1, ah2, ah3, b0.z, b0.w);
        MMA(acc[0], al0, al1, al2, al3, b0.x, b0.y);
        MMA(acc[1], ah0, ah1, ah2, ah3, b1.x, b1.y);
        MMA(acc[1], ah0, ah1, ah2, ah3, b1.z, b1.w);
        MMA(acc[1], al0, al1, al2, al3, b1.x, b1.y);
        MMA(acc[2], ah0, ah1, ah2, ah3, b2.x, b2.y);
        MMA(acc[2], ah0, ah1, ah2, ah3, b2.z, b2.w);
        MMA(acc[2], al0, al1, al2, al3, b2.x, b2.y);
    }

#pragma unroll
    for (int nt = 0; nt < 3; nt++) {
        int col = nt * 8 + (lane & 3) * 2;
        *(float2*)&g_hpart[bk][r0][col] = make_float2(acc[nt][0], acc[nt][1]);
        *(float2*)&g_hpart[bk][r1][col] = make_float2(acc[nt][2], acc[nt][3]);
    }
    ss0 += __shfl_xor_sync(0xffffffffu, ss0, 1);
    ss0 += __shfl_xor_sync(0xffffffffu, ss0, 2);
    ss1 += __shfl_xor_sync(0xffffffffu, ss1, 1);
    ss1 += __shfl_xor_sync(0xffffffffu, ss1, 2);
    if ((lane & 3) == 0) {
        g_sspart[bk][r0] = ss0;
        g_sspart[bk][r1] = ss1;
    }
}

// ---------------------------------------------------------------------------
// Kernel B: reduce partials, activations, Sinkhorn. Early-exit RESTORED
// (R15/16 showed it does fire: fixed-400 was slightly slower). Tree-form
// dots; check every 8 iters via multiply-compare; cap 400 = MAX_IT^2.
// ---------------------------------------------------------------------------
extern "C" __global__ void __launch_bounds__(32)
mhc_finish_kernel(const float* __restrict__ bias, const float* __restrict__ alpha,
                  float* __restrict__ out) {
    int row = blockIdx.x * 32 + threadIdx.x;

    float h[N_OUT];
#pragma unroll
    for (int n = 0; n < N_OUT; n++) h[n] = 0.f;
#pragma unroll
    for (int c = 0; c < KSPLIT; c++) {
        const float4* hp = (const float4*)g_hpart[c][row];
#pragma unroll
        for (int q = 0; q < 6; q++) {
            float4 v4 = hp[q];
            h[q * 4 + 0] += v4.x;
            h[q * 4 + 1] += v4.y;
            h[q * 4 + 2] += v4.z;
            h[q * 4 + 3] += v4.w;
        }
    }
    float ss = 0.f;
#pragma unroll
    for (int c = 0; c < KSPLIT; c++) ss += g_sspart[c][row];

    float r_inv = rsqrtf(ss * (1.0f / K_DIM));
    float a0 = alpha[0], a1 = alpha[1], a2 = alpha[2];

    float pre[HCN], post[HCN], H[HCN][HCN];
#pragma unroll
    for (int n = 0; n < HCN; n++) {
        float z0 = fmaf(r_inv * a0, h[n], bias[n]);
        pre[n] = 1.f / (1.f + __expf(-z0));
        float z1 = fmaf(r_inv * a1, h[HCN + n], bias[HCN + n]);
        post[n] = 2.f / (1.f + __expf(-z1));
    }
#pragma unroll
    for (int i = 0; i < HCN; i++)
#pragma unroll
        for (int j = 0; j < HCN; j++) {
            float z = fmaf(r_inv * a2, h[8 + 4 * i + j], bias[8 + 4 * i + j]);
            H[i][j] = __expf(z);
        }

    const float EPSV = 1e-12f;
    float u0 = 1.f, u1 = 1.f, u2 = 1.f, u3 = 1.f;
    float v0 = 1.f, v1 = 1.f, v2 = 1.f, v3 = 1.f;
    for (int o = 0; o < 50; o++) {          // 50 x 8 = 400 max
        float p0 = v0, p1 = v1, p2 = v2, p3 = v3;
#pragma unroll
        for (int s = 0; s < 8; s++) {
            float a_0 = fmaf(H[0][1], v1, H[0][0] * v0);
            float b_0 = fmaf(H[0][3], v3, fmaf(H[0][2], v2, EPSV));
            float a_1 = fmaf(H[1][1], v1, H[1][0] * v0);
            float b_1 = fmaf(H[1][3], v3, fmaf(H[1][2], v2, EPSV));
            float a_2 = fmaf(H[2][1], v1, H[2][0] * v0);
            float b_2 = fmaf(H[2][3], v3, fmaf(H[2][2], v2, EPSV));
            float a_3 = fmaf(H[3][1], v1, H[3][0] * v0);
            float b_3 = fmaf(H[3][3], v3, fmaf(H[3][2], v2, EPSV));
            u0 = frcp(a_0 + b_0);
            u1 = frcp(a_1 + b_1);
            u2 = frcp(a_2 + b_2);
            u3 = frcp(a_3 + b_3);
            float c_0 = fmaf(H[1][0], u1, H[0][0] * u0);
            float d_0 = fmaf(H[3][0], u3, fmaf(H[2][0], u2, EPSV));
            float c_1 = fmaf(H[1][1], u1, H[0][1] * u0);
            float d_1 = fmaf(H[3][1], u3, fmaf(H[2][1], u2, EPSV));
            float c_2 = fmaf(H[1][2], u1, H[0][2] * u0);
            float d_2 = fmaf(H[3][2], u3, fmaf(H[2][2], u2, EPSV));
            float c_3 = fmaf(H[1][3], u1, H[0][3] * u0);
            float d_3 = fmaf(H[3][3], u3, fmaf(H[2][3], u2, EPSV));
            v0 = frcp(c_0 + d_0);
            v1 = frcp(c_1 + d_1);
            v2 = frcp(c_2 + d_2);
            v3 = frcp(c_3 + d_3);
        }
        float m = fabsf(v0 - p0) - 1e-6f * fabsf(v0);
        m = fmaxf(m, fabsf(v1 - p1) - 1e-6f * fabsf(v1));
        m = fmaxf(m, fabsf(v2 - p2) - 1e-6f * fabsf(v2));
        m = fmaxf(m, fabsf(v3 - p3) - 1e-6f * fabsf(v3));
        if (m <= 0.f) break;
    }

    float u[4] = {u0, u1, u2, u3};
    float v[4] = {v0, v1, v2, v3};

    ((float4*)out)[row] = make_float4(pre[0], pre[1], pre[2], pre[3]);
    ((float4*)(out + (size_t)T_DIM * HCN))[row] =
        make_float4(post[0], post[1], post[2], post[3]);
    float4* res = (float4*)(out + 2 * (size_t)T_DIM * HCN + (size_t)row * 16);
#pragma unroll
    for (int i = 0; i < 4; i++) {
        res[i] = make_float4(u[i] * H[i][0] * v[0], u[i] * H[i][1] * v[1],
                             u[i] * H[i][2] * v[2], u[i] * H[i][3] * v[3]);
    }
}

// ---------------------------------------------------------------------------
extern "C" void kernel_launch(void* const* d_in, const int* in_sizes, int n_in,
                              void* d_out, int out_size) {
    const float* x = (const float*)d_in[0];
    const float* w = (const float*)d_in[1];
    const float* bias = (const float*)d_in[2];
    const float* alpha = (const float*)d_in[3];
    float* out = (float*)d_out;

    mhc_wconv_kernel<<<128, 256>>>(w);
    mhc_gemm_kernel<<<dim3(T_DIM / MB, KSPLIT), NTHREADS>>>(x);
    mhc_finish_kernel<<<T_DIM / 32, 32>>>(bias, alpha, out);
}